// round 1
// baseline (speedup 1.0000x reference)
#include <cuda_runtime.h>
#include <cuda_bf16.h>
#include <cstdint>

// Problem constants
#define B_SZ 4
#define L_SZ 2048
#define DM   1024
#define H_N  16
#define DK   64
#define BH   (B_SZ * H_N)     // 64
#define ROWS (B_SZ * L_SZ)    // 8192
#define EPS_Z 1e-8f

// ---------------- scratch (device globals; no allocation allowed) ----------
__device__ float g_Qp[ROWS * DM];       // 32 MB  fm(q @ Wq^T)
__device__ float g_Kp[ROWS * DM];       // 32 MB  fm(k @ Wk^T)
__device__ float g_Vp[ROWS * DM];       // 32 MB  v @ Wv^T
__device__ float g_Mid[ROWS * DM];      // 32 MB  attention core output
#define NSPLIT 8
__device__ float g_kv_part[NSPLIT * BH * DK * DK];   // 8 MB
__device__ float g_ks_part[NSPLIT * BH * DK];
__device__ float g_KV[BH * DK * DK];
__device__ float g_Ksum[BH * DK];

// ---------------- helpers ---------------------------------------------------
__device__ __forceinline__ float feature_map(float x) {
    // elu(x) + 1
    return x > 0.0f ? x + 1.0f : expf(x);
}

__device__ __forceinline__ void cp_async16(void* smem, const void* gmem) {
    uint32_t s = (uint32_t)__cvta_generic_to_shared(smem);
    asm volatile("cp.async.cg.shared.global [%0], [%1], 16;\n" :: "r"(s), "l"(gmem));
}
__device__ __forceinline__ void cp_commit() {
    asm volatile("cp.async.commit_group;\n");
}

__device__ __forceinline__ uint32_t f2tf32(float x) {
    uint32_t r;
    asm("cvt.rna.tf32.f32 %0, %1;" : "=r"(r) : "f"(x));
    return r;
}

__device__ __forceinline__ void mma_tf32(float* d, const uint32_t* a, const uint32_t* b) {
    asm volatile(
        "mma.sync.aligned.m16n8k8.row.col.f32.tf32.tf32.f32 "
        "{%0,%1,%2,%3},{%4,%5,%6,%7},{%8,%9},{%0,%1,%2,%3};\n"
        : "+f"(d[0]), "+f"(d[1]), "+f"(d[2]), "+f"(d[3])
        : "r"(a[0]), "r"(a[1]), "r"(a[2]), "r"(a[3]),
          "r"(b[0]), "r"(b[1]));
}

// ---------------- tf32 GEMM: C[M,N] = act( A[M,K] @ W[N,K]^T ) --------------
// BM=128 BN=128 BK=16, 256 threads (8 warps, 2x4), warp tile 64x32,
// mma m16n8k8 (4 m-tiles x 4 n-tiles per warp, 2 k-steps per BK).
#define GBM 128
#define GBN 128
#define GBK 16
#define GPAD 4
#define GLD (GBK + GPAD)   // 20 floats: stride 20 -> conflict-free frag gather

template <int ACT>
__global__ __launch_bounds__(256, 2)
void gemm_tf32_kernel(const float* __restrict__ A, const float* __restrict__ W,
                      float* __restrict__ C, int M, int N, int K)
{
    __shared__ float As[2][GBM * GLD];
    __shared__ float Bs[2][GBN * GLD];

    const int bm0 = blockIdx.y * GBM;
    const int bn0 = blockIdx.x * GBN;
    const int tid = threadIdx.x;
    const int wid = tid >> 5;
    const int lane = tid & 31;
    const int wm = wid >> 2;    // 0..1
    const int wn = wid & 3;     // 0..3
    const int gid = lane >> 2;  // 0..7
    const int tig = lane & 3;   // 0..3

    const float* Ag = A + (size_t)bm0 * K;
    const float* Wg = W + (size_t)bn0 * K;

    float acc[4][4][4];
#pragma unroll
    for (int mi = 0; mi < 4; mi++)
#pragma unroll
        for (int ni = 0; ni < 4; ni++)
#pragma unroll
            for (int c = 0; c < 4; c++) acc[mi][ni][c] = 0.0f;

    const int KT = K / GBK;

    // prefetch tile 0
    {
#pragma unroll
        for (int j = 0; j < 2; j++) {
            int i = tid + j * 256;          // 0..511
            int r = i >> 2;                 // 0..127
            int c = (i & 3) * 4;            // 0,4,8,12
            cp_async16(&As[0][r * GLD + c], Ag + (size_t)r * K + c);
            cp_async16(&Bs[0][r * GLD + c], Wg + (size_t)r * K + c);
        }
        cp_commit();
    }

    for (int kt = 0; kt < KT; kt++) {
        const int cur = kt & 1;
        if (kt + 1 < KT) {
            const int nxt = cur ^ 1;
            const int k0 = (kt + 1) * GBK;
#pragma unroll
            for (int j = 0; j < 2; j++) {
                int i = tid + j * 256;
                int r = i >> 2;
                int c = (i & 3) * 4;
                cp_async16(&As[nxt][r * GLD + c], Ag + (size_t)r * K + k0 + c);
                cp_async16(&Bs[nxt][r * GLD + c], Wg + (size_t)r * K + k0 + c);
            }
            cp_commit();
            asm volatile("cp.async.wait_group 1;\n");
        } else {
            asm volatile("cp.async.wait_group 0;\n");
        }
        __syncthreads();

        const float* Asc = As[cur];
        const float* Bsc = Bs[cur];

#pragma unroll
        for (int ks = 0; ks < 2; ks++) {
            const int kb = ks * 8;
            uint32_t af[4][4];
            uint32_t bf[4][2];
#pragma unroll
            for (int mi = 0; mi < 4; mi++) {
                int r = wm * 64 + mi * 16 + gid;
                af[mi][0] = f2tf32(Asc[r * GLD + kb + tig]);
                af[mi][1] = f2tf32(Asc[(r + 8) * GLD + kb + tig]);
                af[mi][2] = f2tf32(Asc[r * GLD + kb + tig + 4]);
                af[mi][3] = f2tf32(Asc[(r + 8) * GLD + kb + tig + 4]);
            }
#pragma unroll
            for (int ni = 0; ni < 4; ni++) {
                int r = wn * 32 + ni * 8 + gid;
                bf[ni][0] = f2tf32(Bsc[r * GLD + kb + tig]);
                bf[ni][1] = f2tf32(Bsc[r * GLD + kb + tig + 4]);
            }
#pragma unroll
            for (int mi = 0; mi < 4; mi++)
#pragma unroll
                for (int ni = 0; ni < 4; ni++)
                    mma_tf32(acc[mi][ni], af[mi], bf[ni]);
        }
        __syncthreads();
    }

    // epilogue
#pragma unroll
    for (int mi = 0; mi < 4; mi++) {
        int r0 = bm0 + wm * 64 + mi * 16 + gid;
#pragma unroll
        for (int ni = 0; ni < 4; ni++) {
            int c0 = bn0 + wn * 32 + ni * 8 + tig * 2;
            float v0 = acc[mi][ni][0];
            float v1 = acc[mi][ni][1];
            float v2 = acc[mi][ni][2];
            float v3 = acc[mi][ni][3];
            if (ACT) {
                v0 = feature_map(v0); v1 = feature_map(v1);
                v2 = feature_map(v2); v3 = feature_map(v3);
            }
            *(float2*)&C[(size_t)r0 * N + c0]       = make_float2(v0, v1);
            *(float2*)&C[(size_t)(r0 + 8) * N + c0] = make_float2(v2, v3);
        }
    }
}

// ---------------- per-head KV = K^T V (split over L) ------------------------
// grid (NSPLIT, BH), 256 threads. Each thread owns (d = tid>>2, 16 m's).
__global__ __launch_bounds__(256)
void kv_partial_kernel(const float* __restrict__ Kp, const float* __restrict__ Vp)
{
    const int s  = blockIdx.x;
    const int bh = blockIdx.y;
    const int b  = bh >> 4;
    const int h  = bh & 15;
    __shared__ float Ks[32 * 64];
    __shared__ float Vs[32 * 64];

    const int tid = threadIdx.x;
    const int dt = tid >> 2;
    const int m0 = (tid & 3) * 16;

    const float* Kg = Kp + ((size_t)(b * L_SZ + s * (L_SZ / NSPLIT))) * DM + h * DK;
    const float* Vg = Vp + ((size_t)(b * L_SZ + s * (L_SZ / NSPLIT))) * DM + h * DK;

    float acc[16];
#pragma unroll
    for (int j = 0; j < 16; j++) acc[j] = 0.0f;
    float sk = 0.0f;

    for (int ch = 0; ch < (L_SZ / NSPLIT) / 32; ch++) {
        const int nbase = ch * 32;
#pragma unroll
        for (int j = 0; j < 8; j++) {
            int i = tid + j * 256;    // 0..2047
            int n = i >> 6, d = i & 63;
            Ks[i] = Kg[(size_t)(nbase + n) * DM + d];
            Vs[i] = Vg[(size_t)(nbase + n) * DM + d];
        }
        __syncthreads();
#pragma unroll 4
        for (int n = 0; n < 32; n++) {
            float kd = Ks[n * 64 + dt];
            sk += kd;
#pragma unroll
            for (int j = 0; j < 16; j++) acc[j] += kd * Vs[n * 64 + m0 + j];
        }
        __syncthreads();
    }

    float* out = g_kv_part + ((size_t)(s * BH + bh)) * (DK * DK);
#pragma unroll
    for (int j = 0; j < 16; j++) out[dt * DK + m0 + j] = acc[j];
    if ((tid & 3) == 0) g_ks_part[(s * BH + bh) * DK + dt] = sk;
}

__global__ __launch_bounds__(256)
void kv_combine_kernel()
{
    const int bh = blockIdx.x;
    const int t = threadIdx.x;
#pragma unroll
    for (int j = 0; j < 16; j++) {
        int e = t + j * 256;
        float sum = 0.0f;
#pragma unroll
        for (int s = 0; s < NSPLIT; s++)
            sum += g_kv_part[((size_t)(s * BH + bh)) * (DK * DK) + e];
        g_KV[(size_t)bh * (DK * DK) + e] = sum;
    }
    if (t < DK) {
        float sum = 0.0f;
#pragma unroll
        for (int s = 0; s < NSPLIT; s++)
            sum += g_ks_part[(s * BH + bh) * DK + t];
        g_Ksum[bh * DK + t] = sum;
    }
}

// ---------------- out = Z * (Q @ KV) ----------------------------------------
// grid (L/64, BH), 256 threads; each thread: one row r=tid>>2, 16 m outputs.
__global__ __launch_bounds__(256)
void attn_apply_kernel(const float* __restrict__ Qp, float* __restrict__ Mid)
{
    const int lc = blockIdx.x;
    const int bh = blockIdx.y;
    const int b = bh >> 4;
    const int h = bh & 15;

    __shared__ float KVs[DK * DK];
    __shared__ float Qs[64 * 65];
    __shared__ float Kss[DK];

    const int tid = threadIdx.x;
    const float* Qg = Qp + ((size_t)(b * L_SZ + lc * 64)) * DM + h * DK;

#pragma unroll
    for (int j = 0; j < 16; j++) {
        int i = tid + j * 256;          // 0..4095
        KVs[i] = g_KV[(size_t)bh * (DK * DK) + i];
        int r = i >> 6, d = i & 63;
        Qs[r * 65 + d] = Qg[(size_t)r * DM + d];
    }
    if (tid < DK) Kss[tid] = g_Ksum[bh * DK + tid];
    __syncthreads();

    const int r = tid >> 2;
    const int m0 = (tid & 3) * 16;

    float dot = 0.0f;
#pragma unroll
    for (int d = 0; d < DK; d++) dot += Qs[r * 65 + d] * Kss[d];
    const float z = 1.0f / (dot + EPS_Z);

    float acc[16];
#pragma unroll
    for (int j = 0; j < 16; j++) acc[j] = 0.0f;
#pragma unroll 8
    for (int d = 0; d < DK; d++) {
        float qd = Qs[r * 65 + d];
#pragma unroll
        for (int j = 0; j < 16; j++) acc[j] += qd * KVs[d * 64 + m0 + j];
    }

    float* Og = Mid + ((size_t)(b * L_SZ + lc * 64 + r)) * DM + h * DK + m0;
#pragma unroll
    for (int j4 = 0; j4 < 4; j4++) {
        float4 v = make_float4(acc[j4 * 4] * z, acc[j4 * 4 + 1] * z,
                               acc[j4 * 4 + 2] * z, acc[j4 * 4 + 3] * z);
        *(float4*)&Og[j4 * 4] = v;
    }
}

// ---------------- launch ----------------------------------------------------
extern "C" void kernel_launch(void* const* d_in, const int* in_sizes, int n_in,
                              void* d_out, int out_size)
{
    const float* q  = (const float*)d_in[0];
    const float* k  = (const float*)d_in[1];
    const float* v  = (const float*)d_in[2];
    // d_in[3] = mask (all ones, unused in linear branch)
    const float* wq = (const float*)d_in[4];
    const float* wk = (const float*)d_in[5];
    const float* wv = (const float*)d_in[6];
    const float* wo = (const float*)d_in[7];
    float* out = (float*)d_out;

    float *Qp, *Kp, *Vp, *Mid;
    cudaGetSymbolAddress((void**)&Qp,  g_Qp);
    cudaGetSymbolAddress((void**)&Kp,  g_Kp);
    cudaGetSymbolAddress((void**)&Vp,  g_Vp);
    cudaGetSymbolAddress((void**)&Mid, g_Mid);

    dim3 ggrid(DM / GBN, ROWS / GBM);   // (8, 64)

    gemm_tf32_kernel<1><<<ggrid, 256>>>(q, wq, Qp, ROWS, DM, DM);
    gemm_tf32_kernel<1><<<ggrid, 256>>>(k, wk, Kp, ROWS, DM, DM);
    gemm_tf32_kernel<0><<<ggrid, 256>>>(v, wv, Vp, ROWS, DM, DM);

    kv_partial_kernel<<<dim3(NSPLIT, BH), 256>>>(Kp, Vp);
    kv_combine_kernel<<<BH, 256>>>();
    attn_apply_kernel<<<dim3(L_SZ / 64, BH), 256>>>(Qp, Mid);

    gemm_tf32_kernel<0><<<ggrid, 256>>>(Mid, wo, out, ROWS, DM, DM);
}

// round 3
// speedup vs baseline: 1.1026x; 1.1026x over previous
#include <cuda_runtime.h>
#include <cstdint>

#define B_SZ 4
#define L_SZ 2048
#define DM   1024
#define H_N  16
#define DK   64
#define BH   64
#define ROWS 8192
#define EPS_Z 1e-8f
#define NSPLIT 16

// ---------------- scratch ----------------------------------------------------
__device__ float g_Qp[ROWS * DM];
__device__ float g_Kp[ROWS * DM];
__device__ float g_Vp[ROWS * DM];
__device__ float g_Mid[ROWS * DM];
__device__ float g_Wc[4][DM * DM];
__device__ float g_kv_part[NSPLIT * BH * DK * DK];
__device__ float g_ks_part[NSPLIT * BH * DK];
__device__ float g_KV[BH * DK * DK];
__device__ float g_Ksum[BH * DK];

// ---------------- helpers ----------------------------------------------------
__device__ __forceinline__ float feature_map(float x) {
    return x > 0.0f ? x + 1.0f : expf(x);
}
__device__ __forceinline__ uint32_t su32(const void* p) {
    uint32_t a;
    asm("{ .reg .u64 t; cvta.to.shared.u64 t, %1; cvt.u32.u64 %0, t; }" : "=r"(a) : "l"(p));
    return a;
}
__device__ __forceinline__ uint32_t f2tf32(float x) {
    uint32_t r;
    asm("cvt.rna.tf32.f32 %0, %1;" : "=r"(r) : "f"(x));
    return r;
}
#define CP16(s, g) asm volatile("cp.async.cg.shared.global [%0], [%1], 16;" :: "r"(s), "l"(g))
#define CP_COMMIT() asm volatile("cp.async.commit_group;")

__device__ __forceinline__ void mma_tf32(float* d, const uint32_t* a, const uint32_t* b) {
    asm volatile(
        "mma.sync.aligned.m16n8k8.row.col.f32.tf32.tf32.f32 "
        "{%0,%1,%2,%3},{%4,%5,%6,%7},{%8,%9},{%0,%1,%2,%3};\n"
        : "+f"(d[0]), "+f"(d[1]), "+f"(d[2]), "+f"(d[3])
        : "r"(a[0]), "r"(a[1]), "r"(a[2]), "r"(a[3]),
          "r"(b[0]), "r"(b[1]));
}

// ---------------- tf32 GEMM: C[M,N] = act( A[M,K] @ W[N,K]^T ) ---------------
// BM=128 BN=256 BK=32, 256 threads (8 warps 2x4), warp tile 64x64.
// B (weights) is pre-rounded to tf32; A optionally cvt'd in-kernel (ACVT).
#define GBM 128
#define GBN 256
#define GBK 32
#define GPAD 4
#define GLD (GBK + GPAD)                    // 36 floats/row -> conflict-free
#define A_FLOATS (GBM * GLD)                // 4608
#define B_FLOATS (GBN * GLD)                // 9216
#define STG_FLOATS (A_FLOATS + B_FLOATS)    // 13824
#define GSMEM (2 * STG_FLOATS * 4)          // 110592 B

template <int ACT, int ACVT>
__global__ __launch_bounds__(256, 1)
void gemm_tc(const float* __restrict__ A, const float* __restrict__ W,
             float* __restrict__ C)
{
    extern __shared__ __align__(16) float sm[];

    const int tid = threadIdx.x;
    const int wid = tid >> 5;
    const int lane = tid & 31;
    const int wm = wid >> 2;     // 0..1
    const int wn = wid & 3;      // 0..3
    const int gid = lane >> 2;   // 0..7
    const int tig = lane & 3;    // 0..3
    const int bm0 = blockIdx.y * GBM;
    const int bn0 = blockIdx.x * GBN;

    const float* Ag = A + (size_t)bm0 * DM;
    const float* Wg = W + (size_t)bn0 * DM;
    const uint32_t sbase = su32(sm);

    float acc[4][8][4];
#pragma unroll
    for (int mi = 0; mi < 4; mi++)
#pragma unroll
        for (int ni = 0; ni < 8; ni++)
#pragma unroll
            for (int c = 0; c < 4; c++) acc[mi][ni][c] = 0.0f;

    auto load_tile = [&](int stg, int k0) {
        const uint32_t ab = sbase + stg * (STG_FLOATS * 4);
        const uint32_t bb = ab + A_FLOATS * 4;
#pragma unroll
        for (int j = 0; j < 4; j++) {           // A: 1024 x 16B chunks
            int i = tid + j * 256;
            int r = i >> 3, q = i & 7;
            CP16(ab + (r * GLD + q * 4) * 4, Ag + (size_t)r * DM + k0 + q * 4);
        }
#pragma unroll
        for (int j = 0; j < 8; j++) {           // B: 2048 x 16B chunks
            int i = tid + j * 256;
            int r = i >> 3, q = i & 7;
            CP16(bb + (r * GLD + q * 4) * 4, Wg + (size_t)r * DM + k0 + q * 4);
        }
        CP_COMMIT();
    };

    const int KT = DM / GBK;    // 32
    load_tile(0, 0);

    for (int t = 0; t < KT; t++) {
        const int cur = t & 1;
        if (t + 1 < KT) {
            load_tile(cur ^ 1, (t + 1) * GBK);
            asm volatile("cp.async.wait_group 1;");
        } else {
            asm volatile("cp.async.wait_group 0;");
        }
        __syncthreads();

        const float* Asf = sm + cur * STG_FLOATS;
        const float* Bsf = Asf + A_FLOATS;
        const uint32_t* Asu = (const uint32_t*)Asf;
        const uint32_t* Bsu = (const uint32_t*)Bsf;

#pragma unroll
        for (int ks = 0; ks < 4; ks++) {
            const int kb = ks * 8;
            uint32_t af[4][4];
            uint32_t bf[8][2];
#pragma unroll
            for (int mi = 0; mi < 4; mi++) {
                int r = wm * 64 + mi * 16 + gid;
                int b0 = r * GLD + kb + tig;
                if (ACVT) {
                    af[mi][0] = f2tf32(Asf[b0]);
                    af[mi][1] = f2tf32(Asf[b0 + 8 * GLD]);
                    af[mi][2] = f2tf32(Asf[b0 + 4]);
                    af[mi][3] = f2tf32(Asf[b0 + 8 * GLD + 4]);
                } else {
                    af[mi][0] = Asu[b0];
                    af[mi][1] = Asu[b0 + 8 * GLD];
                    af[mi][2] = Asu[b0 + 4];
                    af[mi][3] = Asu[b0 + 8 * GLD + 4];
                }
            }
#pragma unroll
            for (int ni = 0; ni < 8; ni++) {
                int r = wn * 64 + ni * 8 + gid;
                bf[ni][0] = Bsu[r * GLD + kb + tig];
                bf[ni][1] = Bsu[r * GLD + kb + tig + 4];
            }
#pragma unroll
            for (int mi = 0; mi < 4; mi++)
#pragma unroll
                for (int ni = 0; ni < 8; ni++)
                    mma_tf32(acc[mi][ni], af[mi], bf[ni]);
        }
        __syncthreads();
    }

    // epilogue
#pragma unroll
    for (int mi = 0; mi < 4; mi++) {
        int r0 = bm0 + wm * 64 + mi * 16 + gid;
#pragma unroll
        for (int ni = 0; ni < 8; ni++) {
            int c0 = bn0 + wn * 64 + ni * 8 + tig * 2;
            float v0 = acc[mi][ni][0];
            float v1 = acc[mi][ni][1];
            float v2 = acc[mi][ni][2];
            float v3 = acc[mi][ni][3];
            if (ACT) {
                v0 = feature_map(v0); v1 = feature_map(v1);
                v2 = feature_map(v2); v3 = feature_map(v3);
            }
            *(float2*)&C[(size_t)r0 * DM + c0]       = make_float2(v0, v1);
            *(float2*)&C[(size_t)(r0 + 8) * DM + c0] = make_float2(v2, v3);
        }
    }
}

// ---------------- weight rna pre-round ---------------------------------------
__global__ __launch_bounds__(256)
void cvt_rna_kernel(const float* __restrict__ in, float* __restrict__ out)
{
    int i = blockIdx.x * 256 + threadIdx.x;
    float4 v = ((const float4*)in)[i];
    float4 r;
    r.x = __uint_as_float(f2tf32(v.x));
    r.y = __uint_as_float(f2tf32(v.y));
    r.z = __uint_as_float(f2tf32(v.z));
    r.w = __uint_as_float(f2tf32(v.w));
    ((float4*)out)[i] = r;
}

// ---------------- per-head KV = K^T V (split over L) -------------------------
__global__ __launch_bounds__(256)
void kv_partial_kernel(const float* __restrict__ Kp, const float* __restrict__ Vp)
{
    const int s  = blockIdx.x;
    const int bh = blockIdx.y;
    const int b  = bh >> 4;
    const int h  = bh & 15;
    __shared__ float Ks[32 * 64];
    __shared__ float Vs[32 * 64];

    const int tid = threadIdx.x;
    const int dt = tid >> 2;
    const int mq = tid & 3;

    const size_t rb = ((size_t)(b * L_SZ + s * (L_SZ / NSPLIT))) * DM + h * DK;
    const float* Kg = Kp + rb;
    const float* Vg = Vp + rb;

    float4 a0 = {0,0,0,0}, a1 = {0,0,0,0}, a2 = {0,0,0,0}, a3 = {0,0,0,0};
    float sk = 0.0f;

    for (int ch = 0; ch < (L_SZ / NSPLIT) / 32; ch++) {
#pragma unroll
        for (int j = 0; j < 2; j++) {
            int i = tid + j * 256;
            int n = i >> 4, q = i & 15;
            ((float4*)Ks)[i] = *(const float4*)&Kg[(size_t)(ch * 32 + n) * DM + q * 4];
            ((float4*)Vs)[i] = *(const float4*)&Vg[(size_t)(ch * 32 + n) * DM + q * 4];
        }
        __syncthreads();
#pragma unroll 4
        for (int n = 0; n < 32; n++) {
            float kd = Ks[n * 64 + dt];
            sk += kd;
            const float4* vr = (const float4*)&Vs[n * 64 + mq * 16];
            float4 v0 = vr[0], v1 = vr[1], v2 = vr[2], v3 = vr[3];
            a0.x += kd * v0.x; a0.y += kd * v0.y; a0.z += kd * v0.z; a0.w += kd * v0.w;
            a1.x += kd * v1.x; a1.y += kd * v1.y; a1.z += kd * v1.z; a1.w += kd * v1.w;
            a2.x += kd * v2.x; a2.y += kd * v2.y; a2.z += kd * v2.z; a2.w += kd * v2.w;
            a3.x += kd * v3.x; a3.y += kd * v3.y; a3.z += kd * v3.z; a3.w += kd * v3.w;
        }
        __syncthreads();
    }

    float4* o = (float4*)(g_kv_part + ((size_t)(s * BH + bh)) * (DK * DK) + dt * DK + mq * 16);
    o[0] = a0; o[1] = a1; o[2] = a2; o[3] = a3;
    if (mq == 0) g_ks_part[(s * BH + bh) * DK + dt] = sk;
}

__global__ __launch_bounds__(256)
void kv_combine_kernel()
{
    const int bh = blockIdx.x;
    const int t = threadIdx.x;
#pragma unroll
    for (int j = 0; j < 16; j++) {
        int e = t + j * 256;
        float sum = 0.0f;
#pragma unroll
        for (int s = 0; s < NSPLIT; s++)
            sum += g_kv_part[((size_t)(s * BH + bh)) * (DK * DK) + e];
        g_KV[(size_t)bh * (DK * DK) + e] = sum;
    }
    if (t < DK) {
        float sum = 0.0f;
#pragma unroll
        for (int s = 0; s < NSPLIT; s++)
            sum += g_ks_part[(s * BH + bh) * DK + t];
        g_Ksum[bh * DK + t] = sum;
    }
}

// ---------------- Mid = rna( Z * (Q @ KV) ) ----------------------------------
__global__ __launch_bounds__(256)
void attn_apply_kernel(const float* __restrict__ Qp, float* __restrict__ Mid)
{
    const int lc = blockIdx.x;
    const int bh = blockIdx.y;
    const int b = bh >> 4;
    const int h = bh & 15;

    __shared__ float KVs[DK * DK];
    __shared__ float Qs[64 * 68];
    __shared__ float Kss[DK];

    const int tid = threadIdx.x;
    const float* Qg = Qp + ((size_t)(b * L_SZ + lc * 64)) * DM + h * DK;

#pragma unroll
    for (int j = 0; j < 4; j++) {
        int i = tid + j * 256;
        ((float4*)KVs)[i] = ((const float4*)(g_KV + (size_t)bh * (DK * DK)))[i];
        int r = i >> 4, q = i & 15;
        *(float4*)&Qs[r * 68 + q * 4] = *(const float4*)&Qg[(size_t)r * DM + q * 4];
    }
    if (tid < DK) Kss[tid] = g_Ksum[bh * DK + tid];
    __syncthreads();

    const int r = tid >> 2;
    const int mq = tid & 3;

    float dot = 0.0f;
#pragma unroll
    for (int d = 0; d < DK; d++) dot += Qs[r * 68 + d] * Kss[d];
    const float z = 1.0f / (dot + EPS_Z);

    float4 a0 = {0,0,0,0}, a1 = {0,0,0,0}, a2 = {0,0,0,0}, a3 = {0,0,0,0};
#pragma unroll 8
    for (int d = 0; d < DK; d++) {
        float qd = Qs[r * 68 + d];
        const float4* kv = (const float4*)&KVs[d * 64 + mq * 16];
        float4 v0 = kv[0], v1 = kv[1], v2 = kv[2], v3 = kv[3];
        a0.x += qd * v0.x; a0.y += qd * v0.y; a0.z += qd * v0.z; a0.w += qd * v0.w;
        a1.x += qd * v1.x; a1.y += qd * v1.y; a1.z += qd * v1.z; a1.w += qd * v1.w;
        a2.x += qd * v2.x; a2.y += qd * v2.y; a2.z += qd * v2.z; a2.w += qd * v2.w;
        a3.x += qd * v3.x; a3.y += qd * v3.y; a3.z += qd * v3.z; a3.w += qd * v3.w;
    }

    float* Og = Mid + ((size_t)(b * L_SZ + lc * 64 + r)) * DM + h * DK + mq * 16;
    float4 o;
#define STORE4(aa, off) \
    o.x = __uint_as_float(f2tf32(aa.x * z)); \
    o.y = __uint_as_float(f2tf32(aa.y * z)); \
    o.z = __uint_as_float(f2tf32(aa.z * z)); \
    o.w = __uint_as_float(f2tf32(aa.w * z)); \
    *(float4*)&Og[off] = o;
    STORE4(a0, 0); STORE4(a1, 4); STORE4(a2, 8); STORE4(a3, 12);
#undef STORE4
}

// ---------------- launch -----------------------------------------------------
extern "C" void kernel_launch(void* const* d_in, const int* in_sizes, int n_in,
                              void* d_out, int out_size)
{
    const float* q  = (const float*)d_in[0];
    const float* k  = (const float*)d_in[1];
    const float* v  = (const float*)d_in[2];
    const float* wq = (const float*)d_in[4];
    const float* wk = (const float*)d_in[5];
    const float* wv = (const float*)d_in[6];
    const float* wo = (const float*)d_in[7];
    float* out = (float*)d_out;

    float *Qp, *Kp, *Vp, *Mid, *Wc;
    cudaGetSymbolAddress((void**)&Qp,  g_Qp);
    cudaGetSymbolAddress((void**)&Kp,  g_Kp);
    cudaGetSymbolAddress((void**)&Vp,  g_Vp);
    cudaGetSymbolAddress((void**)&Mid, g_Mid);
    cudaGetSymbolAddress((void**)&Wc,  g_Wc);

    cudaFuncSetAttribute(gemm_tc<1,1>, cudaFuncAttributeMaxDynamicSharedMemorySize, GSMEM);
    cudaFuncSetAttribute(gemm_tc<0,1>, cudaFuncAttributeMaxDynamicSharedMemorySize, GSMEM);
    cudaFuncSetAttribute(gemm_tc<0,0>, cudaFuncAttributeMaxDynamicSharedMemorySize, GSMEM);

    const int nc = (DM * DM) / 4 / 256;   // 1024 blocks
    cvt_rna_kernel<<<nc, 256>>>(wq, Wc + 0 * DM * DM);
    cvt_rna_kernel<<<nc, 256>>>(wk, Wc + 1 * DM * DM);
    cvt_rna_kernel<<<nc, 256>>>(wv, Wc + 2 * DM * DM);
    cvt_rna_kernel<<<nc, 256>>>(wo, Wc + 3 * DM * DM);

    dim3 ggrid(DM / GBN, ROWS / GBM);     // (4, 64)
    gemm_tc<1,1><<<ggrid, 256, GSMEM>>>(q, Wc + 0 * DM * DM, Qp);
    gemm_tc<1,1><<<ggrid, 256, GSMEM>>>(k, Wc + 1 * DM * DM, Kp);
    gemm_tc<0,1><<<ggrid, 256, GSMEM>>>(v, Wc + 2 * DM * DM, Vp);

    kv_partial_kernel<<<dim3(NSPLIT, BH), 256>>>(Kp, Vp);
    kv_combine_kernel<<<BH, 256>>>();
    attn_apply_kernel<<<dim3(L_SZ / 64, BH), 256>>>(Qp, Mid);

    gemm_tc<0,0><<<ggrid, 256, GSMEM>>>(Mid, Wc + 3 * DM * DM, out);
}

// round 4
// speedup vs baseline: 1.5607x; 1.4155x over previous
#include <cuda_runtime.h>
#include <cuda_fp16.h>
#include <cstdint>

#define B_SZ 4
#define L_SZ 2048
#define DM   1024
#define H_N  16
#define DK   64
#define BH   64
#define ROWS 8192
#define EPS_Z 1e-8f
#define NSPLIT 16

// ---------------- scratch ----------------------------------------------------
__device__ __half g_Wh[4][DM * DM];        // fp16 weights (wq,wk,wv,wo)
__device__ __half g_Ah[3][ROWS * DM];      // fp16 inputs (q,k,v)
__device__ __half g_Qp[ROWS * DM];
__device__ __half g_Kp[ROWS * DM];
__device__ __half g_Vp[ROWS * DM];
__device__ __half g_Mid[ROWS * DM];
__device__ float  g_kv_part[NSPLIT * BH * DK * DK];
__device__ float  g_ks_part[NSPLIT * BH * DK];
__device__ float  g_KV[BH * DK * DK];
__device__ float  g_Ksum[BH * DK];

// ---------------- helpers ----------------------------------------------------
__device__ __forceinline__ float feature_map(float x) {
    return x > 0.0f ? x + 1.0f : expf(x);
}
__device__ __forceinline__ uint32_t su32(const void* p) {
    uint32_t a;
    asm("{ .reg .u64 t; cvta.to.shared.u64 t, %1; cvt.u32.u64 %0, t; }" : "=r"(a) : "l"(p));
    return a;
}
#define CP16(s, g) asm volatile("cp.async.cg.shared.global [%0], [%1], 16;" :: "r"(s), "l"(g))
#define CP_COMMIT() asm volatile("cp.async.commit_group;")
#define SWZ(o) ((o) ^ (((o) >> 3) & 0x70))   // 128B-row swizzle, conflict-free

__device__ __forceinline__ void ldm_x4(uint32_t* r, uint32_t addr) {
    asm volatile("ldmatrix.sync.aligned.m8n8.x4.shared.b16 {%0,%1,%2,%3}, [%4];"
                 : "=r"(r[0]), "=r"(r[1]), "=r"(r[2]), "=r"(r[3]) : "r"(addr));
}
__device__ __forceinline__ void mma_f16(float* d, const uint32_t* a, const uint32_t* b) {
    asm volatile(
        "mma.sync.aligned.m16n8k16.row.col.f32.f16.f16.f32 "
        "{%0,%1,%2,%3},{%4,%5,%6,%7},{%8,%9},{%0,%1,%2,%3};\n"
        : "+f"(d[0]), "+f"(d[1]), "+f"(d[2]), "+f"(d[3])
        : "r"(a[0]), "r"(a[1]), "r"(a[2]), "r"(a[3]),
          "r"(b[0]), "r"(b[1]));
}

// ---------------- fp16 GEMM: C = act( A[M,K] @ W[N,K]^T ) --------------------
// BM=128 BN=256 BK=64(halfs,128B rows), 256 threads (8 warps 2x4), warp 64x64.
#define GBM 128
#define GBN 256
#define GBK 64
#define ABYTES (GBM * 128)        // 16384
#define BBYTES (GBN * 128)        // 32768
#define STAGEB (ABYTES + BBYTES)  // 49152
#define GSMEM  (2 * STAGEB)       // 98304

// OUTK: 0 = fp32 out, 1 = fp16 out.  ACT: elu+1 on result.
template <int ACT, int OUTK>
__global__ __launch_bounds__(256, 1)
void gemm_f16(const __half* __restrict__ A, const __half* __restrict__ W,
              void* __restrict__ Cv)
{
    extern __shared__ __align__(16) char sm[];

    const int tid = threadIdx.x;
    const int wid = tid >> 5;
    const int lane = tid & 31;
    const int wm = wid >> 2;      // 0..1
    const int wn = wid & 3;       // 0..3
    const int gid = lane >> 2;    // 0..7
    const int tig = lane & 3;     // 0..3
    const int bm0 = blockIdx.y * GBM;
    const int bn0 = blockIdx.x * GBN;

    const __half* Ag = A + (size_t)bm0 * DM;
    const __half* Wg = W + (size_t)bn0 * DM;
    const uint32_t sbase = su32(sm);

    float acc[4][8][4];
#pragma unroll
    for (int mi = 0; mi < 4; mi++)
#pragma unroll
        for (int ni = 0; ni < 8; ni++)
#pragma unroll
            for (int c = 0; c < 4; c++) acc[mi][ni][c] = 0.0f;

    auto load_tile = [&](int stg, int k0) {
        const uint32_t ab = sbase + stg * STAGEB;
        const uint32_t bb = ab + ABYTES;
#pragma unroll
        for (int j = 0; j < 4; j++) {          // A: 1024 x 16B chunks
            int i = tid + j * 256;
            int r = i >> 3, q = i & 7;
            CP16(ab + SWZ(r * 128 + q * 16), Ag + (size_t)r * DM + k0 + q * 8);
        }
#pragma unroll
        for (int j = 0; j < 8; j++) {          // B: 2048 x 16B chunks
            int i = tid + j * 256;
            int r = i >> 3, q = i & 7;
            CP16(bb + SWZ(r * 128 + q * 16), Wg + (size_t)r * DM + k0 + q * 8);
        }
        CP_COMMIT();
    };

    const int KT = DM / GBK;   // 16
    load_tile(0, 0);

    // per-lane ldmatrix row/byte offsets
    const int lrow = lane & 15;
    const int lhi  = (lane >> 4) << 4;       // 0 or 16 bytes

    for (int t = 0; t < KT; t++) {
        const int cur = t & 1;
        if (t + 1 < KT) {
            load_tile(cur ^ 1, (t + 1) * GBK);
            asm volatile("cp.async.wait_group 1;");
        } else {
            asm volatile("cp.async.wait_group 0;");
        }
        __syncthreads();

        const uint32_t ab = sbase + cur * STAGEB;
        const uint32_t bb = ab + ABYTES;

#pragma unroll
        for (int ks = 0; ks < 4; ks++) {       // k-steps of 16 halfs (32B)
            const int kboff = ks * 32 + lhi;
            uint32_t af[4][4];
            uint32_t bf[4][4];                 // [pair][4 regs = b0 nt0, b0 nt1, b1 nt0, b1 nt1]
#pragma unroll
            for (int mi = 0; mi < 4; mi++) {
                int row = wm * 64 + mi * 16 + lrow;
                ldm_x4(af[mi], ab + SWZ(row * 128 + kboff));
            }
#pragma unroll
            for (int p = 0; p < 4; p++) {
                int row = wn * 64 + p * 16 + lrow;
                ldm_x4(bf[p], bb + SWZ(row * 128 + kboff));
            }
#pragma unroll
            for (int mi = 0; mi < 4; mi++)
#pragma unroll
                for (int p = 0; p < 4; p++) {
                    uint32_t b0[2] = { bf[p][0], bf[p][2] };   // n-tile 2p
                    uint32_t b1[2] = { bf[p][1], bf[p][3] };   // n-tile 2p+1
                    mma_f16(acc[mi][2 * p + 0], af[mi], b0);
                    mma_f16(acc[mi][2 * p + 1], af[mi], b1);
                }
        }
        __syncthreads();
    }

    // epilogue
#pragma unroll
    for (int mi = 0; mi < 4; mi++) {
        int r0 = bm0 + wm * 64 + mi * 16 + gid;
#pragma unroll
        for (int ni = 0; ni < 8; ni++) {
            int c0 = bn0 + wn * 64 + ni * 8 + tig * 2;
            float v0 = acc[mi][ni][0];
            float v1 = acc[mi][ni][1];
            float v2 = acc[mi][ni][2];
            float v3 = acc[mi][ni][3];
            if (ACT) {
                v0 = feature_map(v0); v1 = feature_map(v1);
                v2 = feature_map(v2); v3 = feature_map(v3);
            }
            if (OUTK) {
                __half* C = (__half*)Cv;
                *(__half2*)&C[(size_t)r0 * DM + c0]       = __floats2half2_rn(v0, v1);
                *(__half2*)&C[(size_t)(r0 + 8) * DM + c0] = __floats2half2_rn(v2, v3);
            } else {
                float* C = (float*)Cv;
                *(float2*)&C[(size_t)r0 * DM + c0]       = make_float2(v0, v1);
                *(float2*)&C[(size_t)(r0 + 8) * DM + c0] = make_float2(v2, v3);
            }
        }
    }
}

// ---------------- fp32 -> fp16 converts --------------------------------------
// weights: 4 matrices in one launch (blockIdx.y selects)
__global__ __launch_bounds__(256)
void wcvt_kernel(const float* __restrict__ w0, const float* __restrict__ w1,
                 const float* __restrict__ w2, const float* __restrict__ w3)
{
    const float* src[4] = { w0, w1, w2, w3 };
    const float* in = src[blockIdx.y];
    __half* out = g_Wh[blockIdx.y];
    int i = blockIdx.x * 256 + threadIdx.x;          // float4 index
    float4 v = ((const float4*)in)[i];
    __half2 h0 = __floats2half2_rn(v.x, v.y);
    __half2 h1 = __floats2half2_rn(v.z, v.w);
    ((__half2*)out)[2 * i]     = h0;
    ((__half2*)out)[2 * i + 1] = h1;
}

__global__ __launch_bounds__(256)
void acvt_kernel(const float* __restrict__ in, __half* __restrict__ out)
{
    int i = blockIdx.x * 256 + threadIdx.x;          // float4 index
    float4 v = ((const float4*)in)[i];
    ((__half2*)out)[2 * i]     = __floats2half2_rn(v.x, v.y);
    ((__half2*)out)[2 * i + 1] = __floats2half2_rn(v.z, v.w);
}

// ---------------- per-head KV = K^T V (split over L), fp16 in ---------------
__global__ __launch_bounds__(256)
void kv_partial_kernel(const __half* __restrict__ Kp, const __half* __restrict__ Vp)
{
    const int s  = blockIdx.x;
    const int bh = blockIdx.y;
    const int b  = bh >> 4;
    const int h  = bh & 15;
    __shared__ float Ks[32 * 64];
    __shared__ float Vs[32 * 64];

    const int tid = threadIdx.x;
    const int dt = tid >> 2;
    const int mq = tid & 3;

    const size_t rb = ((size_t)(b * L_SZ + s * (L_SZ / NSPLIT))) * DM + h * DK;
    const __half* Kg = Kp + rb;
    const __half* Vg = Vp + rb;

    float4 a0 = {0,0,0,0}, a1 = {0,0,0,0}, a2 = {0,0,0,0}, a3 = {0,0,0,0};
    float sk = 0.0f;

    const int n = tid >> 3;            // 0..31
    const int qc = (tid & 7) * 8;      // 8-half chunk

    for (int ch = 0; ch < (L_SZ / NSPLIT) / 32; ch++) {
        {
            union { uint4 u; __half2 h[4]; } UK, UV;
            UK.u = *(const uint4*)&Kg[(size_t)(ch * 32 + n) * DM + qc];
            UV.u = *(const uint4*)&Vg[(size_t)(ch * 32 + n) * DM + qc];
#pragma unroll
            for (int j = 0; j < 4; j++) {
                float2 fk = __half22float2(UK.h[j]);
                float2 fv = __half22float2(UV.h[j]);
                Ks[n * 64 + qc + 2 * j]     = fk.x;
                Ks[n * 64 + qc + 2 * j + 1] = fk.y;
                Vs[n * 64 + qc + 2 * j]     = fv.x;
                Vs[n * 64 + qc + 2 * j + 1] = fv.y;
            }
        }
        __syncthreads();
#pragma unroll 4
        for (int nn = 0; nn < 32; nn++) {
            float kd = Ks[nn * 64 + dt];
            sk += kd;
            const float4* vr = (const float4*)&Vs[nn * 64 + mq * 16];
            float4 v0 = vr[0], v1 = vr[1], v2 = vr[2], v3 = vr[3];
            a0.x += kd * v0.x; a0.y += kd * v0.y; a0.z += kd * v0.z; a0.w += kd * v0.w;
            a1.x += kd * v1.x; a1.y += kd * v1.y; a1.z += kd * v1.z; a1.w += kd * v1.w;
            a2.x += kd * v2.x; a2.y += kd * v2.y; a2.z += kd * v2.z; a2.w += kd * v2.w;
            a3.x += kd * v3.x; a3.y += kd * v3.y; a3.z += kd * v3.z; a3.w += kd * v3.w;
        }
        __syncthreads();
    }

    float4* o = (float4*)(g_kv_part + ((size_t)(s * BH + bh)) * (DK * DK) + dt * DK + mq * 16);
    o[0] = a0; o[1] = a1; o[2] = a2; o[3] = a3;
    if (mq == 0) g_ks_part[(s * BH + bh) * DK + dt] = sk;
}

__global__ __launch_bounds__(256)
void kv_combine_kernel()
{
    const int bh = blockIdx.x;
    const int t = threadIdx.x;
#pragma unroll
    for (int j = 0; j < 16; j++) {
        int e = t + j * 256;
        float sum = 0.0f;
#pragma unroll
        for (int s = 0; s < NSPLIT; s++)
            sum += g_kv_part[((size_t)(s * BH + bh)) * (DK * DK) + e];
        g_KV[(size_t)bh * (DK * DK) + e] = sum;
    }
    if (t < DK) {
        float sum = 0.0f;
#pragma unroll
        for (int s = 0; s < NSPLIT; s++)
            sum += g_ks_part[(s * BH + bh) * DK + t];
        g_Ksum[bh * DK + t] = sum;
    }
}

// ---------------- Mid(fp16) = Z * (Q @ KV) ----------------------------------
__global__ __launch_bounds__(256)
void attn_apply_kernel(const __half* __restrict__ Qp, __half* __restrict__ Mid)
{
    const int lc = blockIdx.x;
    const int bh = blockIdx.y;
    const int b = bh >> 4;
    const int h = bh & 15;

    __shared__ float KVs[DK * DK];
    __shared__ float Qs[64 * 68];
    __shared__ float Kss[DK];

    const int tid = threadIdx.x;
    const __half* Qg = Qp + ((size_t)(b * L_SZ + lc * 64)) * DM + h * DK;

#pragma unroll
    for (int j = 0; j < 4; j++) {
        int i = tid + j * 256;
        ((float4*)KVs)[i] = ((const float4*)(g_KV + (size_t)bh * (DK * DK)))[i];
    }
    {
        // load 64x64 halfs -> Qs floats, 8 halfs per thread x 2 iters
#pragma unroll
        for (int j = 0; j < 2; j++) {
            int i = tid + j * 256;         // 0..511 (8-half chunks)
            int r = i >> 3, qc = (i & 7) * 8;
            union { uint4 u; __half2 h[4]; } U;
            U.u = *(const uint4*)&Qg[(size_t)r * DM + qc];
#pragma unroll
            for (int jj = 0; jj < 4; jj++) {
                float2 f = __half22float2(U.h[jj]);
                Qs[r * 68 + qc + 2 * jj]     = f.x;
                Qs[r * 68 + qc + 2 * jj + 1] = f.y;
            }
        }
    }
    if (tid < DK) Kss[tid] = g_Ksum[bh * DK + tid];
    __syncthreads();

    const int r = tid >> 2;
    const int mq = tid & 3;

    float dot = 0.0f;
#pragma unroll
    for (int d = 0; d < DK; d++) dot += Qs[r * 68 + d] * Kss[d];
    const float z = 1.0f / (dot + EPS_Z);

    float4 a0 = {0,0,0,0}, a1 = {0,0,0,0}, a2 = {0,0,0,0}, a3 = {0,0,0,0};
#pragma unroll 8
    for (int d = 0; d < DK; d++) {
        float qd = Qs[r * 68 + d];
        const float4* kv = (const float4*)&KVs[d * 64 + mq * 16];
        float4 v0 = kv[0], v1 = kv[1], v2 = kv[2], v3 = kv[3];
        a0.x += qd * v0.x; a0.y += qd * v0.y; a0.z += qd * v0.z; a0.w += qd * v0.w;
        a1.x += qd * v1.x; a1.y += qd * v1.y; a1.z += qd * v1.z; a1.w += qd * v1.w;
        a2.x += qd * v2.x; a2.y += qd * v2.y; a2.z += qd * v2.z; a2.w += qd * v2.w;
        a3.x += qd * v3.x; a3.y += qd * v3.y; a3.z += qd * v3.z; a3.w += qd * v3.w;
    }

    __half* Og = Mid + ((size_t)(b * L_SZ + lc * 64 + r)) * DM + h * DK + mq * 16;
    union { uint4 u; __half2 h[4]; } O0, O1;
    O0.h[0] = __floats2half2_rn(a0.x * z, a0.y * z);
    O0.h[1] = __floats2half2_rn(a0.z * z, a0.w * z);
    O0.h[2] = __floats2half2_rn(a1.x * z, a1.y * z);
    O0.h[3] = __floats2half2_rn(a1.z * z, a1.w * z);
    O1.h[0] = __floats2half2_rn(a2.x * z, a2.y * z);
    O1.h[1] = __floats2half2_rn(a2.z * z, a2.w * z);
    O1.h[2] = __floats2half2_rn(a3.x * z, a3.y * z);
    O1.h[3] = __floats2half2_rn(a3.z * z, a3.w * z);
    *(uint4*)&Og[0] = O0.u;
    *(uint4*)&Og[8] = O1.u;
}

// ---------------- launch -----------------------------------------------------
extern "C" void kernel_launch(void* const* d_in, const int* in_sizes, int n_in,
                              void* d_out, int out_size)
{
    const float* q  = (const float*)d_in[0];
    const float* k  = (const float*)d_in[1];
    const float* v  = (const float*)d_in[2];
    const float* wq = (const float*)d_in[4];
    const float* wk = (const float*)d_in[5];
    const float* wv = (const float*)d_in[6];
    const float* wo = (const float*)d_in[7];
    float* out = (float*)d_out;

    __half *Wh, *Ah, *Qp, *Kp, *Vp, *Mid;
    cudaGetSymbolAddress((void**)&Wh,  g_Wh);
    cudaGetSymbolAddress((void**)&Ah,  g_Ah);
    cudaGetSymbolAddress((void**)&Qp,  g_Qp);
    cudaGetSymbolAddress((void**)&Kp,  g_Kp);
    cudaGetSymbolAddress((void**)&Vp,  g_Vp);
    cudaGetSymbolAddress((void**)&Mid, g_Mid);

    cudaFuncSetAttribute(gemm_f16<1,1>, cudaFuncAttributeMaxDynamicSharedMemorySize, GSMEM);
    cudaFuncSetAttribute(gemm_f16<0,1>, cudaFuncAttributeMaxDynamicSharedMemorySize, GSMEM);
    cudaFuncSetAttribute(gemm_f16<0,0>, cudaFuncAttributeMaxDynamicSharedMemorySize, GSMEM);

    // launch 1: weights (4 matrices)
    wcvt_kernel<<<dim3((DM * DM) / 4 / 256, 4), 256>>>(wq, wk, wv, wo);
    // launches 2-4: inputs
    const int na = (ROWS * DM) / 4 / 256;   // 8192
    acvt_kernel<<<na, 256>>>(q, Ah + 0 * (size_t)ROWS * DM);
    acvt_kernel<<<na, 256>>>(k, Ah + 1 * (size_t)ROWS * DM);
    acvt_kernel<<<na, 256>>>(v, Ah + 2 * (size_t)ROWS * DM);

    dim3 ggrid(DM / GBN, ROWS / GBM);       // (4, 64)
    // launches 5-7: projections (launch 6 = K GEMM lands under ncu -s 5 -c 1)
    gemm_f16<1,1><<<ggrid, 256, GSMEM>>>(Ah + 0 * (size_t)ROWS * DM, Wh + 0 * (size_t)DM * DM, Qp);
    gemm_f16<1,1><<<ggrid, 256, GSMEM>>>(Ah + 1 * (size_t)ROWS * DM, Wh + 1 * (size_t)DM * DM, Kp);
    gemm_f16<0,1><<<ggrid, 256, GSMEM>>>(Ah + 2 * (size_t)ROWS * DM, Wh + 2 * (size_t)DM * DM, Vp);

    kv_partial_kernel<<<dim3(NSPLIT, BH), 256>>>(Kp, Vp);
    kv_combine_kernel<<<BH, 256>>>();
    attn_apply_kernel<<<dim3(L_SZ / 64, BH), 256>>>(Qp, Mid);

    gemm_f16<0,0><<<ggrid, 256, GSMEM>>>(Mid, Wh + 3 * (size_t)DM * DM, out);
}